// round 2
// baseline (speedup 1.0000x reference)
#include <cuda_runtime.h>
#include <cstdint>
#include <cstddef>

#define NR 8192
#define DI 1024
#define DO 4096
#define C  32
#define KSEL 10
#define GAMMA_F 0.01618f

#define BM 128
#define BN 128
#define BK 8

typedef unsigned long long ull;

// ---------------- static device scratch (no allocations allowed) ------------
__device__ float g_h[(size_t)NR * DO];   // 128 MB: fp32 h = leaky(XW^T + b)
__device__ float g_ch[NR * C];           // refined candidate h values (f32)
__device__ int   g_ci[NR * C];           // candidate column indices
__device__ float g_cT[NR];               // certificate threshold (33rd largest h)

// ---------------- f32x2 helpers --------------------------------------------
__device__ __forceinline__ ull pdup(float v) {
    ull r; asm("mov.b64 %0,{%1,%1};" : "=l"(r) : "f"(v)); return r;
}
__device__ __forceinline__ void ffma2(ull& d, ull a, ull b) {
    asm("fma.rn.f32x2 %0, %1, %2, %0;" : "+l"(d) : "l"(a), "l"(b));
}
__device__ __forceinline__ float2 unp(ull v) {
    float2 f; asm("mov.b64 {%0,%1},%2;" : "=f"(f.x), "=f"(f.y) : "l"(v)); return f;
}

// ---------------- Phase 0: zero the output ---------------------------------
__global__ void zero_kernel(float4* __restrict__ p, int n4) {
    int i = blockIdx.x * blockDim.x + threadIdx.x;
    if (i < n4) p[i] = make_float4(0.f, 0.f, 0.f, 0.f);
}

// ---------------- Phase 1: fp32 GEMM + bias + leaky_relu -------------------
// h[8192,4096] = leaky(X[8192,1024] * W[4096,1024]^T + b)
// 128x128x8 tiles, 256 threads, 8x8 microtile as 8x4 f32x2 accumulators.
// A is stored in smem as duplicated pairs so the inner loop is LDS.128+FFMA2.
__global__ void __launch_bounds__(256, 1)
gemm_kernel(const float* __restrict__ X, const float* __restrict__ W,
            const float* __restrict__ bias) {
    __shared__ ull   As[2][BK][BM + 4];   // 2*8*132*8  = 16896 B
    __shared__ float Bs[2][BK][BN + 4];   // 2*8*132*4  =  8448 B

    const int tid  = threadIdx.x;
    const int row0 = blockIdx.y * BM;
    const int col0 = blockIdx.x * BN;
    const int lr = tid >> 1;            // 0..127
    const int lk = (tid & 1) << 2;      // 0 or 4
    const float* xp = X + (size_t)(row0 + lr) * DI + lk;
    const float* wp = W + (size_t)(col0 + lr) * DI + lk;
    const int tx = tid & 15;            // N-dir
    const int ty = tid >> 4;            // M-dir

    ull acc[8][4];
#pragma unroll
    for (int i = 0; i < 8; ++i)
#pragma unroll
        for (int j = 0; j < 4; ++j) acc[i][j] = 0ULL;

    float4 av4 = *(const float4*)xp;
    float4 bv4 = *(const float4*)wp;

#define GSTORE(sidx)                                          \
    do {                                                      \
        As[sidx][lk + 0][lr] = pdup(av4.x);                   \
        As[sidx][lk + 1][lr] = pdup(av4.y);                   \
        As[sidx][lk + 2][lr] = pdup(av4.z);                   \
        As[sidx][lk + 3][lr] = pdup(av4.w);                   \
        Bs[sidx][lk + 0][lr] = bv4.x;                         \
        Bs[sidx][lk + 1][lr] = bv4.y;                         \
        Bs[sidx][lk + 2][lr] = bv4.z;                         \
        Bs[sidx][lk + 3][lr] = bv4.w;                         \
    } while (0)

    GSTORE(0);
    __syncthreads();

    int st = 0;
    const int NT = DI / BK;  // 128
#pragma unroll 1
    for (int kt = 0; kt < NT; ++kt) {
        float4 na, nb;
        if (kt + 1 < NT) {
            na = *(const float4*)(xp + (kt + 1) * BK);
            nb = *(const float4*)(wp + (kt + 1) * BK);
        }
#pragma unroll
        for (int k = 0; k < BK; ++k) {
            const ull*   ap = &As[st][k][ty * 8];
            const float* bp = &Bs[st][k][tx * 8];
            ull a_[8], b_[4];
            ((ulonglong2*)a_)[0] = ((const ulonglong2*)ap)[0];
            ((ulonglong2*)a_)[1] = ((const ulonglong2*)ap)[1];
            ((ulonglong2*)a_)[2] = ((const ulonglong2*)ap)[2];
            ((ulonglong2*)a_)[3] = ((const ulonglong2*)ap)[3];
            ((ulonglong2*)b_)[0] = *(const ulonglong2*)(bp);
            ((ulonglong2*)b_)[1] = *(const ulonglong2*)(bp + 4);
#pragma unroll
            for (int i = 0; i < 8; ++i)
#pragma unroll
                for (int j = 0; j < 4; ++j) ffma2(acc[i][j], a_[i], b_[j]);
        }
        if (kt + 1 < NT) {
            av4 = na; bv4 = nb;
            st ^= 1;
            GSTORE(st);
            __syncthreads();
        }
    }

    // epilogue: bias + leaky, store to g_h
    float bl[8];
#pragma unroll
    for (int j = 0; j < 8; ++j) bl[j] = bias[col0 + tx * 8 + j];
    const size_t obase = (size_t)(row0 + ty * 8) * DO + col0 + tx * 8;
#pragma unroll
    for (int i = 0; i < 8; ++i) {
        float o[8];
#pragma unroll
        for (int j = 0; j < 4; ++j) {
            float2 p = unp(acc[i][j]);
            o[2 * j] = p.x; o[2 * j + 1] = p.y;
        }
#pragma unroll
        for (int j = 0; j < 8; ++j) {
            float v = o[j] + bl[j];
            o[j] = (v > 0.f) ? v : 0.01f * v;
        }
        float4* dst = (float4*)(g_h + obase + (size_t)i * DO);
        dst[0] = make_float4(o[0], o[1], o[2], o[3]);
        dst[1] = make_float4(o[4], o[5], o[6], o[7]);
    }
#undef GSTORE
}

// ---------------- Phase 2: per-row top-32 candidates (exact radix select) --
__global__ void __launch_bounds__(256)
cand_kernel() {
    const int row = blockIdx.x;
    const int tid = threadIdx.x;
    __shared__ unsigned skey[DO];    // 16 KB
    __shared__ unsigned hist[256];
    __shared__ unsigned s_pref;
    __shared__ int s_need, s_cnt;

    const float* h = g_h + (size_t)row * DO;
    for (int i = tid; i < DO; i += 256) {
        unsigned u = __float_as_uint(h[i]);
        u ^= (u >> 31) ? 0xFFFFFFFFu : 0x80000000u;   // monotonic key
        skey[i] = u;
    }
    if (tid == 0) { s_pref = 0; s_need = C + 1; s_cnt = 0; }
    __syncthreads();

    // find the (C+1)-th largest key via 4x 8-bit radix passes
    for (int pass = 0; pass < 4; ++pass) {
        const int shift = 24 - 8 * pass;
        for (int i = tid; i < 256; i += 256) hist[i] = 0;
        __syncthreads();
        unsigned pref = s_pref;
        unsigned hm = (pass == 0) ? 0u : (0xFFFFFFFFu << (shift + 8));
        for (int i = tid; i < DO; i += 256) {
            unsigned k = skey[i];
            if (((k ^ pref) & hm) == 0) atomicAdd(&hist[(k >> shift) & 255], 1u);
        }
        __syncthreads();
        if (tid == 0) {
            int need = s_need, acc = 0, b = 255;
            for (;; --b) { acc += (int)hist[b]; if (acc >= need) break; }
            s_need = need - (acc - (int)hist[b]);
            s_pref = pref | ((unsigned)b << shift);
        }
        __syncthreads();
    }
    const unsigned K33 = s_pref;

    // collect strictly-greater keys (set is deterministic; order doesn't matter)
    for (int i = tid; i < DO; i += 256) {
        if (skey[i] > K33) {
            int p = atomicAdd(&s_cnt, 1);
            g_ci[row * C + p] = i;
        }
    }
    __syncthreads();
    if (tid == 0) {
        int m = s_cnt;  // <= 32 by rank definition
        for (int i = 0; i < DO && m < C; ++i)   // ties at K33: lowest index first
            if (skey[i] == K33) { g_ci[row * C + m] = i; ++m; }
        g_cT[row] = __float_as_uint(0), g_cT[row] = __uint_as_float(
            (K33 & 0x80000000u) ? (K33 ^ 0x80000000u) : ~K33);
    }
}

// ---------------- Phase 3: compensated-fp32 refinement of candidate h ------
__global__ void __launch_bounds__(1024)
refine_kernel(const float* __restrict__ X, const float* __restrict__ W,
              const float* __restrict__ bias) {
    const int row = blockIdx.x, tid = threadIdx.x;
    const int w = tid >> 5, lane = tid & 31;
    __shared__ float sx[DI];
    sx[tid] = X[(size_t)row * DI + tid];
    __syncthreads();

    const int ci = g_ci[row * C + w];
    const float* wr = W + (size_t)ci * DI;
    float hi = 0.f, lo = 0.f;
#pragma unroll 8
    for (int i = 0; i < DI / 32; ++i) {
        int kk = i * 32 + lane;
        float a = sx[kk], b = wr[kk];
        float p  = __fmul_rn(a, b);
        float pe = __fmaf_rn(a, b, -p);          // exact product error
        float t  = __fadd_rn(hi, p);             // TwoSum
        float bp = __fsub_rn(t, hi);
        float e  = __fadd_rn(__fsub_rn(hi, __fsub_rn(t, bp)), __fsub_rn(p, bp));
        hi = t;
        lo = __fadd_rn(lo, __fadd_rn(e, pe));
    }
    double d = (double)hi + (double)lo;
#pragma unroll
    for (int off = 16; off; off >>= 1) d += __shfl_xor_sync(0xFFFFFFFFu, d, off);
    if (lane == 0) {
        float hv = (float)d;                     // ~= round-to-nearest(exact dot)
        hv = __fadd_rn(hv, bias[ci]);
        hv = (hv > 0.f) ? hv : __fmul_rn(0.01f, hv);
        g_ch[row * C + w] = hv;
    }
}

// ---------------- Phase 4: sequential recurrence (one warp) ----------------
__device__ __noinline__ void fallback_row(float* __restrict__ out, int t,
                                          int* s_lr, const float* s_chain,
                                          int lane) {
    // exact full-row top-10 (rare path)
    float fs[DO / 32];
#pragma unroll 4
    for (int i = 0; i < DO / 32; ++i) {
        int col = i * 32 + lane;
        int lr = s_lr[col];
        int m = t - lr - 1; if (m > 63) m = 63;
        fs[i] = __fmul_rn(g_h[(size_t)t * DO + col], s_chain[m]);
    }
    for (int r = 0; r < KSEL; ++r) {
        float bv = -3.4e38f; int bc = DO;
        for (int i = 0; i < DO / 32; ++i) {
            int col = i * 32 + lane;
            float v = fs[i];
            if (v > bv || (v == bv && col < bc)) { bv = v; bc = col; }
        }
        for (int off = 16; off; off >>= 1) {
            float ov = __shfl_xor_sync(0xFFFFFFFFu, bv, off);
            int   oc = __shfl_xor_sync(0xFFFFFFFFu, bc, off);
            if (ov > bv || (ov == bv && oc < bc)) { bv = ov; bc = oc; }
        }
        if (!(bv > 0.f)) break;                  // remaining picks are <= 0
        if ((bc & 31) == lane) fs[bc >> 5] = -3.4e38f;
        if (lane == 0) { out[(size_t)t * DO + bc] = 1.0f; s_lr[bc] = t; }
        __syncwarp();
    }
    __syncwarp();
}

__global__ void __launch_bounds__(32)
seq_kernel(float* __restrict__ out) {
    __shared__ int   s_lr[DO];       // last reset row per column
    __shared__ float s_chain[64];    // exact repeated-add phi table
    const int lane = threadIdx.x;

    for (int i = lane; i < DO; i += 32) s_lr[i] = -1000000;
    if (lane == 0) {
        float c = 0.f;
        s_chain[0] = 0.f;
        for (int i = 1; i < 64; ++i) {
            c = fminf(__fadd_rn(c, GAMMA_F), 1.0f);
            s_chain[i] = c;   // saturates at 1.0 by index 62
        }
    }
    __syncwarp();

    float nh = g_ch[lane]; int ni = g_ci[lane]; float nT = g_cT[0];
    for (int t = 0; t < NR; ++t) {
        const float myh = nh; const int myidx = ni; const float T = nT;
        if (t + 1 < NR) {   // prefetch next row's candidates (hides LDG latency)
            nh = g_ch[(t + 1) * C + lane];
            ni = g_ci[(t + 1) * C + lane];
            nT = g_cT[t + 1];
        }
        int lr = s_lr[myidx];
        int age = t - lr - 1; if (age > 63) age = 63;
        const float s = __fmul_rn(myh, s_chain[age]);

        int cnt = 0;   // strict rank among candidates, top_k tie = lower index
#pragma unroll
        for (int j = 0; j < 32; ++j) {
            float sj = __shfl_sync(0xFFFFFFFFu, s, j);
            int   ij = __shfl_sync(0xFFFFFFFFu, myidx, j);
            cnt += (sj > s) || (sj == s && ij < myidx);
        }
        unsigned m9 = __ballot_sync(0xFFFFFFFFu, cnt == 9);
        float v10 = __shfl_sync(0xFFFFFFFFu, s, __ffs(m9) - 1);

        if (v10 > T + 1e-3f) {   // certificate: candidate top-10 == global top-10
            if (cnt < KSEL && s > 0.f) {
                out[(size_t)t * DO + myidx] = 1.0f;
                s_lr[myidx] = t;
            }
        } else {
            fallback_row(out, t, s_lr, s_chain, lane);
        }
        __syncwarp();
    }
}

// ---------------- launch ----------------------------------------------------
extern "C" void kernel_launch(void* const* d_in, const int* in_sizes, int n_in,
                              void* d_out, int out_size) {
    const float* X    = (const float*)d_in[0];
    const float* W    = (const float*)d_in[1];
    const float* bias = (const float*)d_in[2];
    float* out = (float*)d_out;

    const int n4 = NR * DO / 4;
    zero_kernel<<<(n4 + 255) / 256, 256>>>((float4*)out, n4);

    dim3 gg(DO / BN, NR / BM);
    gemm_kernel<<<gg, 256>>>(X, W, bias);

    cand_kernel<<<NR, 256>>>();
    refine_kernel<<<NR, 1024>>>(X, W, bias);
    seq_kernel<<<1, 32>>>(out);
}